// round 11
// baseline (speedup 1.0000x reference)
#include <cuda_runtime.h>
#include <cstdint>

#define DIMS 128
#define NLAB 5
#define MAXN 50000

// ---------------- device scratch ----------------
__device__ float g_W2[2][DIMS * DIMS];        // W_in@W_in, W_out@W_out (fp32)
__device__ float g_c[2][NLAB];                // per-label gate constants
__device__ float g_gate[2][MAXN];             // per-node h.Wg scalars
__device__ float g_hin[MAXN * DIMS];          // x @ (W_in @ W_in)
__device__ float g_hout[MAXN * DIMS];         // x @ (W_out @ W_out)
__device__ float g_acc[MAXN * DIMS];          // accumulator (xl + scatter sums)

__device__ __forceinline__ float sigmoidf_(float x) {
    return 1.0f / (1.0f + __expf(-x));
}

__device__ __forceinline__ float tf32r(float x) {
    uint32_t u;
    asm("cvt.rna.tf32.f32 %0, %1;" : "=r"(u) : "f"(x));
    return __uint_as_float(u);
}

__device__ __forceinline__ void mma_tf32(float* c, uint32_t a0, uint32_t a1,
                                         uint32_t a2, uint32_t a3,
                                         uint32_t b0, uint32_t b1) {
    asm volatile(
        "mma.sync.aligned.m16n8k8.row.col.f32.tf32.tf32.f32 "
        "{%0,%1,%2,%3}, {%4,%5,%6,%7}, {%8,%9}, {%0,%1,%2,%3};"
        : "+f"(c[0]), "+f"(c[1]), "+f"(c[2]), "+f"(c[3])
        : "r"(a0), "r"(a1), "r"(a2), "r"(a3), "r"(b0), "r"(b1));
}

// ---------------- prep: W2 = W @ W ----------------
__global__ void prep_w2_kernel(const float* __restrict__ Win,
                               const float* __restrict__ Wout) {
    __shared__ float wrow[DIMS];
    const float* W = (blockIdx.y == 0) ? Win : Wout;
    int r = blockIdx.x, c = threadIdx.x;
    wrow[c] = W[r * DIMS + c];
    __syncthreads();
    float s = 0.0f;
#pragma unroll 8
    for (int k = 0; k < DIMS; k++) s += wrow[k] * W[k * DIMS + c];
    g_W2[blockIdx.y][r * DIMS + c] = s;
}

// ---------------- prep: gate constants ----------------
__global__ void prep_c_kernel(const float* __restrict__ Wg_in,
                              const float* __restrict__ blab_in,
                              const float* __restrict__ bg_in,
                              const float* __restrict__ Wg_out,
                              const float* __restrict__ blab_out,
                              const float* __restrict__ bg_out) {
    int t = threadIdx.x;
    if (t >= 2 * NLAB) return;
    int w = t / NLAB, l = t % NLAB;
    const float* Wg = w ? Wg_out : Wg_in;
    const float* bl = w ? blab_out : blab_in;
    const float* bg = w ? bg_out : bg_in;
    float s = bg[l];
    for (int d = 0; d < DIMS; d++) s += bl[l * DIMS + d] * Wg[d];
    g_c[w][l] = s;
}

// ---------------- mma.sync tf32 GEMM (single pass) + fused epilogue ----------------
// blockIdx.y==0: g_acc = gate_loop(x@W_loop + b_loop)
// blockIdx.y==1: g_hin  = x@W2_in,  g_gate[0] = h.Wg_in
// blockIdx.y==2: g_hout = x@W2_out, g_gate[1] = h.Wg_out
//
// smem: As tf32 [128][136]; Wh tf32 [128][136] (B^T, paired (k,k+4) layout)
#define AS_STRIDE 136
#define SMEM_AS 0
#define SMEM_WH (128 * AS_STRIDE)
#define GEMM_SMEM (2 * 128 * AS_STRIDE * 4)

__global__ __launch_bounds__(256) void gemm_mma_kernel(const float* __restrict__ x,
                                                       const float* __restrict__ Wloop,
                                                       const float* __restrict__ b_loop,
                                                       const float* __restrict__ Wg_loop,
                                                       const float* __restrict__ bg_loop,
                                                       const float* __restrict__ Wg_in,
                                                       const float* __restrict__ Wg_out,
                                                       int M) {
    extern __shared__ float smem[];
    float* As = smem + SMEM_AS;
    float* Wh = smem + SMEM_WH;

    const float* W = (blockIdx.y == 0) ? Wloop : g_W2[blockIdx.y - 1];

    int tid = threadIdx.x;
    int wid = tid >> 5, lane = tid & 31;
    int g = lane >> 2, t4 = lane & 3;
    int m0 = blockIdx.x * 128;

    // ---- load W, transpose + tf32 round into paired layout ----
    // For B^T row n: position ks*8 + (kk&3)*2 + (kk>>2) holds k = ks*8+kk
    for (int idx = tid; idx < DIMS * DIMS; idx += 256) {
        int k = idx >> 7, n = idx & 127;
        float v = W[idx];                 // W[k*128 + n], coalesced
        int ks = k >> 3, kk = k & 7;
        int pos = ks * 8 + (kk & 3) * 2 + (kk >> 2);
        Wh[n * AS_STRIDE + pos] = tf32r(v);
    }

    // ---- load x tile, tf32-round once ----
    const float4* x4 = (const float4*)x;
#pragma unroll
    for (int i = 0; i < 16; i++) {
        int fidx = tid + i * 256;
        int r = fidx >> 5, kq = fidx & 31;
        float4 v = make_float4(0.f, 0.f, 0.f, 0.f);
        if (m0 + r < M) v = x4[(size_t)(m0 + r) * 32 + kq];
        v.x = tf32r(v.x); v.y = tf32r(v.y); v.z = tf32r(v.z); v.w = tf32r(v.w);
        *(float4*)&As[r * AS_STRIDE + kq * 4] = v;
    }
    __syncthreads();

    // ---- mainloop: warp tile 16 rows x 128 cols, single tf32 pass ----
    int m0w = wid * 16;
    const float* pa0 = As + (m0w + g) * AS_STRIDE;
    const float* pa1 = As + (m0w + g + 8) * AS_STRIDE;

    float acc[16][4];
#pragma unroll
    for (int j = 0; j < 16; j++)
#pragma unroll
        for (int q = 0; q < 4; q++) acc[j][q] = 0.0f;

#pragma unroll 4
    for (int ks = 0; ks < 16; ks++) {
        int k0 = ks * 8;
        uint32_t a0 = __float_as_uint(pa0[k0 + t4]);
        uint32_t a1 = __float_as_uint(pa1[k0 + t4]);
        uint32_t a2 = __float_as_uint(pa0[k0 + t4 + 4]);
        uint32_t a3 = __float_as_uint(pa1[k0 + t4 + 4]);
#pragma unroll
        for (int j = 0; j < 16; j++) {
            int boff = (j * 8 + g) * AS_STRIDE + k0 + t4 * 2;
            float2 bh = *(const float2*)&Wh[boff];
            mma_tf32(acc[j], a0, a1, a2, a3,
                     __float_as_uint(bh.x), __float_as_uint(bh.y));
        }
    }

    // ---- epilogue ----
    // thread owns rows r0 = m0+m0w+g, r1 = r0+8; cols j*8 + t4*2 (+1)
    int r0 = m0 + m0w + g;
    int r1 = r0 + 8;

    if (blockIdx.y == 0) {
        float p0 = 0.f, p1 = 0.f;
#pragma unroll
        for (int j = 0; j < 16; j++) {
            int c0 = j * 8 + t4 * 2;
            float2 bl2 = *(const float2*)&b_loop[c0];
            float2 wg2 = *(const float2*)&Wg_loop[c0];
            acc[j][0] += bl2.x; acc[j][1] += bl2.y;
            acc[j][2] += bl2.x; acc[j][3] += bl2.y;
            p0 += acc[j][0] * wg2.x + acc[j][1] * wg2.y;
            p1 += acc[j][2] * wg2.x + acc[j][3] * wg2.y;
        }
        p0 += __shfl_xor_sync(0xffffffffu, p0, 1);
        p0 += __shfl_xor_sync(0xffffffffu, p0, 2);
        p1 += __shfl_xor_sync(0xffffffffu, p1, 1);
        p1 += __shfl_xor_sync(0xffffffffu, p1, 2);
        float bgv = __ldg(&bg_loop[0]);
        float g0 = sigmoidf_(p0 + bgv);
        float g1 = sigmoidf_(p1 + bgv);
#pragma unroll
        for (int j = 0; j < 16; j++) {
            int c0 = j * 8 + t4 * 2;
            if (r0 < M)
                *(float2*)&g_acc[(size_t)r0 * 128 + c0] = make_float2(g0 * acc[j][0], g0 * acc[j][1]);
            if (r1 < M)
                *(float2*)&g_acc[(size_t)r1 * 128 + c0] = make_float2(g1 * acc[j][2], g1 * acc[j][3]);
        }
    } else {
        int dir = blockIdx.y - 1;
        const float* Wg = dir ? Wg_out : Wg_in;
        float* outp = dir ? g_hout : g_hin;
        float p0 = 0.f, p1 = 0.f;
#pragma unroll
        for (int j = 0; j < 16; j++) {
            int c0 = j * 8 + t4 * 2;
            float2 wg2 = *(const float2*)&Wg[c0];
            p0 += acc[j][0] * wg2.x + acc[j][1] * wg2.y;
            p1 += acc[j][2] * wg2.x + acc[j][3] * wg2.y;
            if (r0 < M)
                *(float2*)&outp[(size_t)r0 * 128 + c0] = make_float2(acc[j][0], acc[j][1]);
            if (r1 < M)
                *(float2*)&outp[(size_t)r1 * 128 + c0] = make_float2(acc[j][2], acc[j][3]);
        }
        p0 += __shfl_xor_sync(0xffffffffu, p0, 1);
        p0 += __shfl_xor_sync(0xffffffffu, p0, 2);
        p1 += __shfl_xor_sync(0xffffffffu, p1, 1);
        p1 += __shfl_xor_sync(0xffffffffu, p1, 2);
        if (t4 == 0) {
            if (r0 < M) g_gate[dir][r0] = p0;
            if (r1 < M) g_gate[dir][r1] = p1;
        }
    }
}

// ---------------- fused edge scatter: 4 edges per warp, vec4 atomics ----------------
__global__ void edge_fused_kernel(const int* __restrict__ src,
                                  const int* __restrict__ dst,
                                  const int* __restrict__ lab,
                                  const float* __restrict__ blab_in,
                                  const float* __restrict__ blab_out,
                                  int E, int N) {
    int gw = (int)((blockIdx.x * (unsigned)blockDim.x + threadIdx.x) >> 5);
    int lane = threadIdx.x & 31;
    int e0 = gw * 4;
    if (e0 >= E) return;
    int cnt = min(4, E - e0);

    int s[4], d[4], l[4];
#pragma unroll
    for (int u = 0; u < 4; u++) {
        int e = e0 + ((u < cnt) ? u : 0);
        s[u] = min(max(src[e], 0), N - 1);
        d[u] = min(max(dst[e], 0), N - 1);
        l[u] = min(max(lab[e], 0), NLAB - 1);
    }

    float gi[4], go[4];
#pragma unroll
    for (int u = 0; u < 4; u++) {
        gi[u] = sigmoidf_(g_gate[0][s[u]] + g_c[0][l[u]]);
        go[u] = sigmoidf_(g_gate[1][d[u]] + g_c[1][l[u]]);
    }

    // issue all 8 long-latency gathers first (MLP)
    float4 mi[4], mo[4];
#pragma unroll
    for (int u = 0; u < 4; u++) {
        mi[u] = ((const float4*)g_hin)[(size_t)s[u] * 32 + lane];
        mo[u] = ((const float4*)g_hout)[(size_t)d[u] * 32 + lane];
    }

#pragma unroll
    for (int u = 0; u < 4; u++) {
        if (u < cnt) {
            float4 bi = ((const float4*)blab_in)[l[u] * 32 + lane];
            float4 bo = ((const float4*)blab_out)[l[u] * 32 + lane];
            float4 vi = make_float4(gi[u] * (mi[u].x + bi.x), gi[u] * (mi[u].y + bi.y),
                                    gi[u] * (mi[u].z + bi.z), gi[u] * (mi[u].w + bi.w));
            float4 vo = make_float4(go[u] * (mo[u].x + bo.x), go[u] * (mo[u].y + bo.y),
                                    go[u] * (mo[u].z + bo.z), go[u] * (mo[u].w + bo.w));
            atomicAdd(((float4*)g_acc) + (size_t)d[u] * 32 + lane, vi);
            atomicAdd(((float4*)g_acc) + (size_t)s[u] * 32 + lane, vo);
        }
    }
}

// ---------------- final relu: g_acc -> d_out ----------------
__global__ void relu_kernel(float* __restrict__ out, int n4) {
    int i = blockIdx.x * blockDim.x + threadIdx.x;
    if (i < n4) {
        float4 v = ((const float4*)g_acc)[i];
        v.x = fmaxf(v.x, 0.f); v.y = fmaxf(v.y, 0.f);
        v.z = fmaxf(v.z, 0.f); v.w = fmaxf(v.w, 0.f);
        ((float4*)out)[i] = v;
    }
}

// ---------------- launch ----------------
extern "C" void kernel_launch(void* const* d_in, const int* in_sizes, int n_in,
                              void* d_out, int out_size) {
    const float* x        = (const float*)d_in[0];
    const int* ei         = (const int*)d_in[1];   // [2, E] int32
    const int* lab        = (const int*)d_in[2];   // [E] int32
    const float* W_loop   = (const float*)d_in[3];
    const float* b_loop   = (const float*)d_in[4];
    const float* Wg_loop  = (const float*)d_in[5];
    const float* bg_loop  = (const float*)d_in[6];
    const float* W_in     = (const float*)d_in[7];
    const float* blab_in  = (const float*)d_in[8];
    const float* Wg_in    = (const float*)d_in[9];
    const float* bg_in    = (const float*)d_in[10];
    const float* W_out    = (const float*)d_in[11];
    const float* blab_out = (const float*)d_in[12];
    const float* Wg_out   = (const float*)d_in[13];
    const float* bg_out   = (const float*)d_in[14];

    int N = in_sizes[0] / DIMS;
    int E = in_sizes[2];

    prep_w2_kernel<<<dim3(DIMS, 2), DIMS>>>(W_in, W_out);
    prep_c_kernel<<<1, 32>>>(Wg_in, blab_in, bg_in, Wg_out, blab_out, bg_out);

    cudaFuncSetAttribute(gemm_mma_kernel, cudaFuncAttributeMaxDynamicSharedMemorySize,
                         GEMM_SMEM);
    gemm_mma_kernel<<<dim3((N + 127) / 128, 3), 256, GEMM_SMEM>>>(
        x, W_loop, b_loop, Wg_loop, bg_loop, Wg_in, Wg_out, N);

    int warps = (E + 3) / 4;
    int eblocks = (warps + 7) / 8;
    edge_fused_kernel<<<eblocks, 256>>>(ei, ei + E, lab, blab_in, blab_out, E, N);

    int n4 = N * DIMS / 4;
    relu_kernel<<<(n4 + 255) / 256, 256>>>((float*)d_out, n4);
}

// round 12
// speedup vs baseline: 1.1903x; 1.1903x over previous
#include <cuda_runtime.h>
#include <cstdint>

#define DIMS 128
#define NLAB 5
#define MAXN 50000

// ---------------- device scratch ----------------
__device__ float g_W2[2][DIMS * DIMS];        // W_in@W_in, W_out@W_out (fp32)
__device__ float g_Wt[3][DIMS * 136];         // prepacked tf32 B^T images (paired layout)
__device__ float g_c[2][NLAB];                // per-label gate constants
__device__ float g_gate[2][MAXN];             // per-node h.Wg scalars
__device__ float g_hin[MAXN * DIMS];          // x @ (W_in @ W_in)
__device__ float g_hout[MAXN * DIMS];         // x @ (W_out @ W_out)
__device__ float g_acc[MAXN * DIMS];          // accumulator (xl + scatter sums)

__device__ __forceinline__ float sigmoidf_(float x) {
    return 1.0f / (1.0f + __expf(-x));
}

__device__ __forceinline__ float tf32r(float x) {
    uint32_t u;
    asm("cvt.rna.tf32.f32 %0, %1;" : "=r"(u) : "f"(x));
    return __uint_as_float(u);
}

__device__ __forceinline__ void mma_tf32(float* c, uint32_t a0, uint32_t a1,
                                         uint32_t a2, uint32_t a3,
                                         uint32_t b0, uint32_t b1) {
    asm volatile(
        "mma.sync.aligned.m16n8k8.row.col.f32.tf32.tf32.f32 "
        "{%0,%1,%2,%3}, {%4,%5,%6,%7}, {%8,%9}, {%0,%1,%2,%3};"
        : "+f"(c[0]), "+f"(c[1]), "+f"(c[2]), "+f"(c[3])
        : "r"(a0), "r"(a1), "r"(a2), "r"(a3), "r"(b0), "r"(b1));
}

// ---------------- prep: W2 = W @ W ----------------
__global__ void prep_w2_kernel(const float* __restrict__ Win,
                               const float* __restrict__ Wout) {
    __shared__ float wrow[DIMS];
    const float* W = (blockIdx.y == 0) ? Win : Wout;
    int r = blockIdx.x, c = threadIdx.x;
    wrow[c] = W[r * DIMS + c];
    __syncthreads();
    float s = 0.0f;
#pragma unroll 8
    for (int k = 0; k < DIMS; k++) s += wrow[k] * W[k * DIMS + c];
    g_W2[blockIdx.y][r * DIMS + c] = s;
}

// ---------------- prep: gate constants ----------------
__global__ void prep_c_kernel(const float* __restrict__ Wg_in,
                              const float* __restrict__ blab_in,
                              const float* __restrict__ bg_in,
                              const float* __restrict__ Wg_out,
                              const float* __restrict__ blab_out,
                              const float* __restrict__ bg_out) {
    int t = threadIdx.x;
    if (t >= 2 * NLAB) return;
    int w = t / NLAB, l = t % NLAB;
    const float* Wg = w ? Wg_out : Wg_in;
    const float* bl = w ? blab_out : blab_in;
    const float* bg = w ? bg_out : bg_in;
    float s = bg[l];
    for (int d = 0; d < DIMS; d++) s += bl[l * DIMS + d] * Wg[d];
    g_c[w][l] = s;
}

// ---------------- prep: paired-layout tf32 W images ----------------
// B^T row n: position ks*8 + (kk&3)*2 + (kk>>2) holds k = ks*8+kk
__global__ void prep_wt_kernel(const float* __restrict__ Wloop) {
    int w = blockIdx.x;
    const float* W = (w == 0) ? Wloop : g_W2[w - 1];
    for (int idx = threadIdx.x; idx < DIMS * DIMS; idx += blockDim.x) {
        int k = idx >> 7, n = idx & 127;
        float v = W[idx];                 // W[k*128 + n], coalesced
        int ks = k >> 3, kk = k & 7;
        int pos = ks * 8 + (kk & 3) * 2 + (kk >> 2);
        g_Wt[w][n * 136 + pos] = tf32r(v);
    }
}

// ---------------- mma.sync tf32 GEMM: one CTA pass over 3 weights ----------------
// w==0: g_acc = gate_loop(x@W_loop + b_loop)
// w==1: g_hin  = x@W2_in,  g_gate[0] = h.Wg_in
// w==2: g_hout = x@W2_out, g_gate[1] = h.Wg_out
#define AS_STRIDE 136
#define SMEM_AS 0
#define SMEM_WH (128 * AS_STRIDE)
#define ST_STRIDE 132
#define GEMM_SMEM (2 * 128 * AS_STRIDE * 4)

__global__ __launch_bounds__(256) void gemm_mma_kernel(const float* __restrict__ x,
                                                       const float* __restrict__ b_loop,
                                                       const float* __restrict__ Wg_loop,
                                                       const float* __restrict__ bg_loop,
                                                       const float* __restrict__ Wg_in,
                                                       const float* __restrict__ Wg_out,
                                                       int M) {
    extern __shared__ float smem[];
    float* As = smem + SMEM_AS;
    float* Wh = smem + SMEM_WH;     // also reused as store-staging buffer

    int tid = threadIdx.x;
    int wid = tid >> 5, lane = tid & 31;
    int g = lane >> 2, t4 = lane & 3;
    int m0 = blockIdx.x * 128;

    // ---- load x tile, tf32-round once ----
    const float4* x4 = (const float4*)x;
#pragma unroll
    for (int i = 0; i < 16; i++) {
        int fidx = tid + i * 256;
        int r = fidx >> 5, kq = fidx & 31;
        float4 v = make_float4(0.f, 0.f, 0.f, 0.f);
        if (m0 + r < M) v = x4[(size_t)(m0 + r) * 32 + kq];
        v.x = tf32r(v.x); v.y = tf32r(v.y); v.z = tf32r(v.z); v.w = tf32r(v.w);
        *(float4*)&As[r * AS_STRIDE + kq * 4] = v;
    }

    int m0w = wid * 16;
    const float* pa0 = As + (m0w + g) * AS_STRIDE;
    const float* pa1 = As + (m0w + g + 8) * AS_STRIDE;
    int r0 = m0 + m0w + g;
    int r1 = r0 + 8;

    for (int w = 0; w < 3; w++) {
        // ---- copy prepacked W image into smem (conflict-free float4) ----
        __syncthreads();
        {
            const float4* srcp = (const float4*)g_Wt[w];
            float4* dstp = (float4*)Wh;
#pragma unroll
            for (int i = 0; i < 17; i++) {
                int fi = tid + i * 256;
                if (fi < 128 * AS_STRIDE / 4) dstp[fi] = srcp[fi];
            }
        }
        __syncthreads();

        // ---- mainloop: warp tile 16 rows x 128 cols ----
        float acc[16][4];
#pragma unroll
        for (int j = 0; j < 16; j++)
#pragma unroll
            for (int q = 0; q < 4; q++) acc[j][q] = 0.0f;

#pragma unroll 4
        for (int ks = 0; ks < 16; ks++) {
            int k0 = ks * 8;
            uint32_t a0 = __float_as_uint(pa0[k0 + t4]);
            uint32_t a1 = __float_as_uint(pa1[k0 + t4]);
            uint32_t a2 = __float_as_uint(pa0[k0 + t4 + 4]);
            uint32_t a3 = __float_as_uint(pa1[k0 + t4 + 4]);
#pragma unroll
            for (int j = 0; j < 16; j++) {
                int boff = (j * 8 + g) * AS_STRIDE + k0 + t4 * 2;
                float2 bh = *(const float2*)&Wh[boff];
                mma_tf32(acc[j], a0, a1, a2, a3,
                         __float_as_uint(bh.x), __float_as_uint(bh.y));
            }
        }

        // ---- per-row gate dots + bias/gating on accumulators ----
        if (w == 0) {
            float p0 = 0.f, p1 = 0.f;
#pragma unroll
            for (int j = 0; j < 16; j++) {
                int c0 = j * 8 + t4 * 2;
                float2 bl2 = *(const float2*)&b_loop[c0];
                float2 wg2 = *(const float2*)&Wg_loop[c0];
                acc[j][0] += bl2.x; acc[j][1] += bl2.y;
                acc[j][2] += bl2.x; acc[j][3] += bl2.y;
                p0 += acc[j][0] * wg2.x + acc[j][1] * wg2.y;
                p1 += acc[j][2] * wg2.x + acc[j][3] * wg2.y;
            }
            p0 += __shfl_xor_sync(0xffffffffu, p0, 1);
            p0 += __shfl_xor_sync(0xffffffffu, p0, 2);
            p1 += __shfl_xor_sync(0xffffffffu, p1, 1);
            p1 += __shfl_xor_sync(0xffffffffu, p1, 2);
            float bgv = __ldg(&bg_loop[0]);
            float g0 = sigmoidf_(p0 + bgv);
            float g1 = sigmoidf_(p1 + bgv);
#pragma unroll
            for (int j = 0; j < 16; j++) {
                acc[j][0] *= g0; acc[j][1] *= g0;
                acc[j][2] *= g1; acc[j][3] *= g1;
            }
        } else {
            int dir = w - 1;
            const float* Wg = dir ? Wg_out : Wg_in;
            float p0 = 0.f, p1 = 0.f;
#pragma unroll
            for (int j = 0; j < 16; j++) {
                int c0 = j * 8 + t4 * 2;
                float2 wg2 = *(const float2*)&Wg[c0];
                p0 += acc[j][0] * wg2.x + acc[j][1] * wg2.y;
                p1 += acc[j][2] * wg2.x + acc[j][3] * wg2.y;
            }
            p0 += __shfl_xor_sync(0xffffffffu, p0, 1);
            p0 += __shfl_xor_sync(0xffffffffu, p0, 2);
            p1 += __shfl_xor_sync(0xffffffffu, p1, 1);
            p1 += __shfl_xor_sync(0xffffffffu, p1, 2);
            if (t4 == 0) {
                if (r0 < M) g_gate[dir][r0] = p0;
                if (r1 < M) g_gate[dir][r1] = p1;
            }
        }

        // ---- stage into smem (Wh reused), then coalesced float4 stores ----
        __syncthreads();   // Wh no longer read by mainloop
        float* stage = Wh;
#pragma unroll
        for (int j = 0; j < 16; j++) {
            int c0 = j * 8 + t4 * 2;
            *(float2*)&stage[(m0w + g) * ST_STRIDE + c0]     = make_float2(acc[j][0], acc[j][1]);
            *(float2*)&stage[(m0w + g + 8) * ST_STRIDE + c0] = make_float2(acc[j][2], acc[j][3]);
        }
        __syncthreads();

        float* outp = (w == 0) ? g_acc : ((w == 1) ? g_hin : g_hout);
#pragma unroll
        for (int i = 0; i < 16; i++) {
            int fidx = tid + i * 256;
            int r = fidx >> 5, cq = fidx & 31;
            int row = m0 + r;
            if (row < M)
                *(float4*)&outp[(size_t)row * 128 + cq * 4] = *(float4*)&stage[r * ST_STRIDE + cq * 4];
        }
    }
}

// ---------------- fused edge scatter: 2 edges per warp, vec4 atomics ----------------
__global__ void edge_fused_kernel(const int* __restrict__ src,
                                  const int* __restrict__ dst,
                                  const int* __restrict__ lab,
                                  const float* __restrict__ blab_in,
                                  const float* __restrict__ blab_out,
                                  int E, int N) {
    int gw = (int)((blockIdx.x * (unsigned)blockDim.x + threadIdx.x) >> 5);
    int lane = threadIdx.x & 31;
    int e0 = gw * 2;
    if (e0 >= E) return;
    int e1 = e0 + 1;
    bool do1 = (e1 < E);
    if (!do1) e1 = e0;

    int s0 = min(max(src[e0], 0), N - 1), d0 = min(max(dst[e0], 0), N - 1);
    int l0 = min(max(lab[e0], 0), NLAB - 1);
    int s1 = min(max(src[e1], 0), N - 1), d1 = min(max(dst[e1], 0), N - 1);
    int l1 = min(max(lab[e1], 0), NLAB - 1);

    float gi0 = sigmoidf_(g_gate[0][s0] + g_c[0][l0]);
    float go0 = sigmoidf_(g_gate[1][d0] + g_c[1][l0]);
    float gi1 = sigmoidf_(g_gate[0][s1] + g_c[0][l1]);
    float go1 = sigmoidf_(g_gate[1][d1] + g_c[1][l1]);

    float4 mi0 = ((const float4*)g_hin)[(size_t)s0 * 32 + lane];
    float4 mo0 = ((const float4*)g_hout)[(size_t)d0 * 32 + lane];
    float4 mi1 = ((const float4*)g_hin)[(size_t)s1 * 32 + lane];
    float4 mo1 = ((const float4*)g_hout)[(size_t)d1 * 32 + lane];

    float4 bi0 = ((const float4*)blab_in)[l0 * 32 + lane];
    float4 bo0 = ((const float4*)blab_out)[l0 * 32 + lane];
    float4 bi1 = ((const float4*)blab_in)[l1 * 32 + lane];
    float4 bo1 = ((const float4*)blab_out)[l1 * 32 + lane];

    float4 vi0 = make_float4(gi0 * (mi0.x + bi0.x), gi0 * (mi0.y + bi0.y),
                             gi0 * (mi0.z + bi0.z), gi0 * (mi0.w + bi0.w));
    float4 vo0 = make_float4(go0 * (mo0.x + bo0.x), go0 * (mo0.y + bo0.y),
                             go0 * (mo0.z + bo0.z), go0 * (mo0.w + bo0.w));
    atomicAdd(((float4*)g_acc) + (size_t)d0 * 32 + lane, vi0);
    atomicAdd(((float4*)g_acc) + (size_t)s0 * 32 + lane, vo0);

    if (do1) {
        float4 vi1 = make_float4(gi1 * (mi1.x + bi1.x), gi1 * (mi1.y + bi1.y),
                                 gi1 * (mi1.z + bi1.z), gi1 * (mi1.w + bi1.w));
        float4 vo1 = make_float4(go1 * (mo1.x + bo1.x), go1 * (mo1.y + bo1.y),
                                 go1 * (mo1.z + bo1.z), go1 * (mo1.w + bo1.w));
        atomicAdd(((float4*)g_acc) + (size_t)d1 * 32 + lane, vi1);
        atomicAdd(((float4*)g_acc) + (size_t)s1 * 32 + lane, vo1);
    }
}

// ---------------- final relu: g_acc -> d_out ----------------
__global__ void relu_kernel(float* __restrict__ out, int n4) {
    int i = blockIdx.x * blockDim.x + threadIdx.x;
    if (i < n4) {
        float4 v = ((const float4*)g_acc)[i];
        v.x = fmaxf(v.x, 0.f); v.y = fmaxf(v.y, 0.f);
        v.z = fmaxf(v.z, 0.f); v.w = fmaxf(v.w, 0.f);
        ((float4*)out)[i] = v;
    }
}

// ---------------- launch ----------------
extern "C" void kernel_launch(void* const* d_in, const int* in_sizes, int n_in,
                              void* d_out, int out_size) {
    const float* x        = (const float*)d_in[0];
    const int* ei         = (const int*)d_in[1];   // [2, E] int32
    const int* lab        = (const int*)d_in[2];   // [E] int32
    const float* W_loop   = (const float*)d_in[3];
    const float* b_loop   = (const float*)d_in[4];
    const float* Wg_loop  = (const float*)d_in[5];
    const float* bg_loop  = (const float*)d_in[6];
    const float* W_in     = (const float*)d_in[7];
    const float* blab_in  = (const float*)d_in[8];
    const float* Wg_in    = (const float*)d_in[9];
    const float* bg_in    = (const float*)d_in[10];
    const float* W_out    = (const float*)d_in[11];
    const float* blab_out = (const float*)d_in[12];
    const float* Wg_out   = (const float*)d_in[13];
    const float* bg_out   = (const float*)d_in[14];

    int N = in_sizes[0] / DIMS;
    int E = in_sizes[2];

    prep_w2_kernel<<<dim3(DIMS, 2), DIMS>>>(W_in, W_out);
    prep_c_kernel<<<1, 32>>>(Wg_in, blab_in, bg_in, Wg_out, blab_out, bg_out);
    prep_wt_kernel<<<3, 256>>>(W_loop);

    cudaFuncSetAttribute(gemm_mma_kernel, cudaFuncAttributeMaxDynamicSharedMemorySize,
                         GEMM_SMEM);
    gemm_mma_kernel<<<(N + 127) / 128, 256, GEMM_SMEM>>>(
        x, b_loop, Wg_loop, bg_loop, Wg_in, Wg_out, N);

    int warps = (E + 1) / 2;
    int eblocks = (warps + 7) / 8;
    edge_fused_kernel<<<eblocks, 256>>>(ei, ei + E, lab, blab_in, blab_out, E, N);

    int n4 = N * DIMS / 4;
    relu_kernel<<<(n4 + 255) / 256, 256>>>((float*)d_out, n4);
}

// round 13
// speedup vs baseline: 1.2510x; 1.0510x over previous
#include <cuda_runtime.h>
#include <cstdint>

#define DIMS 128
#define NLAB 5
#define MAXN 50000
#define GTHREADS 512

// ---------------- device scratch ----------------
__device__ float g_W2[2][DIMS * DIMS];        // W_in@W_in, W_out@W_out (fp32)
__device__ float g_Wt[3][DIMS * 136];         // prepacked tf32 B^T images (paired layout)
__device__ float g_c[2][NLAB];                // per-label gate constants
__device__ float g_gate[2][MAXN];             // per-node h.Wg scalars
__device__ float g_hin[MAXN * DIMS];          // x @ (W_in @ W_in)
__device__ float g_hout[MAXN * DIMS];         // x @ (W_out @ W_out)
__device__ float g_acc[MAXN * DIMS];          // accumulator (xl + scatter sums)

__device__ __forceinline__ float sigmoidf_(float x) {
    return 1.0f / (1.0f + __expf(-x));
}

__device__ __forceinline__ float tf32r(float x) {
    uint32_t u;
    asm("cvt.rna.tf32.f32 %0, %1;" : "=r"(u) : "f"(x));
    return __uint_as_float(u);
}

__device__ __forceinline__ void mma_tf32(float* c, uint32_t a0, uint32_t a1,
                                         uint32_t a2, uint32_t a3,
                                         uint32_t b0, uint32_t b1) {
    asm volatile(
        "mma.sync.aligned.m16n8k8.row.col.f32.tf32.tf32.f32 "
        "{%0,%1,%2,%3}, {%4,%5,%6,%7}, {%8,%9}, {%0,%1,%2,%3};"
        : "+f"(c[0]), "+f"(c[1]), "+f"(c[2]), "+f"(c[3])
        : "r"(a0), "r"(a1), "r"(a2), "r"(a3), "r"(b0), "r"(b1));
}

// ---------------- prep: W2 = W @ W ----------------
__global__ void prep_w2_kernel(const float* __restrict__ Win,
                               const float* __restrict__ Wout) {
    __shared__ float wrow[DIMS];
    const float* W = (blockIdx.y == 0) ? Win : Wout;
    int r = blockIdx.x, c = threadIdx.x;
    wrow[c] = W[r * DIMS + c];
    __syncthreads();
    float s = 0.0f;
#pragma unroll 8
    for (int k = 0; k < DIMS; k++) s += wrow[k] * W[k * DIMS + c];
    g_W2[blockIdx.y][r * DIMS + c] = s;
}

// ---------------- prep: gate constants ----------------
__global__ void prep_c_kernel(const float* __restrict__ Wg_in,
                              const float* __restrict__ blab_in,
                              const float* __restrict__ bg_in,
                              const float* __restrict__ Wg_out,
                              const float* __restrict__ blab_out,
                              const float* __restrict__ bg_out) {
    int t = threadIdx.x;
    if (t >= 2 * NLAB) return;
    int w = t / NLAB, l = t % NLAB;
    const float* Wg = w ? Wg_out : Wg_in;
    const float* bl = w ? blab_out : blab_in;
    const float* bg = w ? bg_out : bg_in;
    float s = bg[l];
    for (int d = 0; d < DIMS; d++) s += bl[l * DIMS + d] * Wg[d];
    g_c[w][l] = s;
}

// ---------------- prep: paired-layout tf32 W images ----------------
// B^T row n: position ks*8 + (kk&3)*2 + (kk>>2) holds k = ks*8+kk
__global__ void prep_wt_kernel(const float* __restrict__ Wloop) {
    int w = blockIdx.x;
    const float* W = (w == 0) ? Wloop : g_W2[w - 1];
    for (int idx = threadIdx.x; idx < DIMS * DIMS; idx += blockDim.x) {
        int k = idx >> 7, n = idx & 127;
        float v = W[idx];                 // W[k*128 + n], coalesced
        int ks = k >> 3, kk = k & 7;
        int pos = ks * 8 + (kk & 3) * 2 + (kk >> 2);
        g_Wt[w][n * 136 + pos] = tf32r(v);
    }
}

// ---------------- mma.sync tf32 GEMM: 512 threads, warp tile 16x64, 3 weights ----------------
#define AS_STRIDE 136
#define SMEM_AS 0
#define SMEM_WH (128 * AS_STRIDE)
#define ST_STRIDE 132
#define GEMM_SMEM (2 * 128 * AS_STRIDE * 4)

__global__ __launch_bounds__(GTHREADS) void gemm_mma_kernel(const float* __restrict__ x,
                                                            const float* __restrict__ b_loop,
                                                            const float* __restrict__ Wg_loop,
                                                            const float* __restrict__ bg_loop,
                                                            const float* __restrict__ Wg_in,
                                                            const float* __restrict__ Wg_out,
                                                            int M) {
    extern __shared__ float smem[];
    float* As = smem + SMEM_AS;
    float* Wh = smem + SMEM_WH;     // reused as store-staging buffer
    __shared__ float sg[DIMS * 2];  // per-row gate-dot partials [row][col-half]

    int tid = threadIdx.x;
    int wid = tid >> 5, lane = tid & 31;
    int g = lane >> 2, t4 = lane & 3;
    int rg = wid & 7;               // row group (16 rows each)
    int ch = wid >> 3;              // column half (64 cols each)
    int m0 = blockIdx.x * 128;
    int m0w = rg * 16;

    // ---- load x tile, tf32-round once ----
    const float4* x4 = (const float4*)x;
#pragma unroll
    for (int i = 0; i < 8; i++) {
        int fidx = tid + i * GTHREADS;
        int r = fidx >> 5, kq = fidx & 31;
        float4 v = make_float4(0.f, 0.f, 0.f, 0.f);
        if (m0 + r < M) v = x4[(size_t)(m0 + r) * 32 + kq];
        v.x = tf32r(v.x); v.y = tf32r(v.y); v.z = tf32r(v.z); v.w = tf32r(v.w);
        *(float4*)&As[r * AS_STRIDE + kq * 4] = v;
    }

    const float* pa0 = As + (m0w + g) * AS_STRIDE;
    const float* pa1 = As + (m0w + g + 8) * AS_STRIDE;
    int rloc0 = m0w + g, rloc1 = rloc0 + 8;
    int r0 = m0 + rloc0, r1 = m0 + rloc1;

    for (int w = 0; w < 3; w++) {
        // ---- copy prepacked W image into smem ----
        __syncthreads();
        {
            const float4* srcp = (const float4*)g_Wt[w];
            float4* dstp = (float4*)Wh;
#pragma unroll
            for (int i = 0; i < 9; i++) {
                int fi = tid + i * GTHREADS;
                if (fi < 128 * AS_STRIDE / 4) dstp[fi] = srcp[fi];
            }
        }
        __syncthreads();

        // ---- mainloop: warp tile 16 rows x 64 cols ----
        float acc[8][4];
#pragma unroll
        for (int j = 0; j < 8; j++)
#pragma unroll
            for (int q = 0; q < 4; q++) acc[j][q] = 0.0f;

#pragma unroll 4
        for (int ks = 0; ks < 16; ks++) {
            int k0 = ks * 8;
            uint32_t a0 = __float_as_uint(pa0[k0 + t4]);
            uint32_t a1 = __float_as_uint(pa1[k0 + t4]);
            uint32_t a2 = __float_as_uint(pa0[k0 + t4 + 4]);
            uint32_t a3 = __float_as_uint(pa1[k0 + t4 + 4]);
#pragma unroll
            for (int j = 0; j < 8; j++) {
                int boff = ((ch * 8 + j) * 8 + g) * AS_STRIDE + k0 + t4 * 2;
                float2 bh = *(const float2*)&Wh[boff];
                mma_tf32(acc[j], a0, a1, a2, a3,
                         __float_as_uint(bh.x), __float_as_uint(bh.y));
            }
        }

        // ---- per-row gate dot partials over this warp's 64 cols ----
        float p0 = 0.f, p1 = 0.f;
        if (w == 0) {
#pragma unroll
            for (int j = 0; j < 8; j++) {
                int c0 = ch * 64 + j * 8 + t4 * 2;
                float2 bl2 = *(const float2*)&b_loop[c0];
                float2 wg2 = *(const float2*)&Wg_loop[c0];
                acc[j][0] += bl2.x; acc[j][1] += bl2.y;
                acc[j][2] += bl2.x; acc[j][3] += bl2.y;
                p0 += acc[j][0] * wg2.x + acc[j][1] * wg2.y;
                p1 += acc[j][2] * wg2.x + acc[j][3] * wg2.y;
            }
        } else {
            const float* Wg = (w == 2) ? Wg_out : Wg_in;
#pragma unroll
            for (int j = 0; j < 8; j++) {
                int c0 = ch * 64 + j * 8 + t4 * 2;
                float2 wg2 = *(const float2*)&Wg[c0];
                p0 += acc[j][0] * wg2.x + acc[j][1] * wg2.y;
                p1 += acc[j][2] * wg2.x + acc[j][3] * wg2.y;
            }
        }
        p0 += __shfl_xor_sync(0xffffffffu, p0, 1);
        p0 += __shfl_xor_sync(0xffffffffu, p0, 2);
        p1 += __shfl_xor_sync(0xffffffffu, p1, 1);
        p1 += __shfl_xor_sync(0xffffffffu, p1, 2);
        if (t4 == 0) {
            sg[rloc0 * 2 + ch] = p0;
            sg[rloc1 * 2 + ch] = p1;
        }
        __syncthreads();   // sg visible; also all Wh reads complete

        if (w == 0) {
            float bgv = __ldg(&bg_loop[0]);
            float g0 = sigmoidf_(sg[rloc0 * 2] + sg[rloc0 * 2 + 1] + bgv);
            float g1 = sigmoidf_(sg[rloc1 * 2] + sg[rloc1 * 2 + 1] + bgv);
#pragma unroll
            for (int j = 0; j < 8; j++) {
                acc[j][0] *= g0; acc[j][1] *= g0;
                acc[j][2] *= g1; acc[j][3] *= g1;
            }
        } else {
            int dir = w - 1;
            if (tid < DIMS) {
                int row = m0 + tid;
                if (row < M) g_gate[dir][row] = sg[tid * 2] + sg[tid * 2 + 1];
            }
        }

        // ---- stage into smem (Wh reused), then coalesced float4 stores ----
        float* stage = Wh;
#pragma unroll
        for (int j = 0; j < 8; j++) {
            int c0 = ch * 64 + j * 8 + t4 * 2;
            *(float2*)&stage[rloc0 * ST_STRIDE + c0] = make_float2(acc[j][0], acc[j][1]);
            *(float2*)&stage[rloc1 * ST_STRIDE + c0] = make_float2(acc[j][2], acc[j][3]);
        }
        __syncthreads();

        float* outp = (w == 0) ? g_acc : ((w == 1) ? g_hin : g_hout);
#pragma unroll
        for (int i = 0; i < 8; i++) {
            int fidx = tid + i * GTHREADS;
            int r = fidx >> 5, cq = fidx & 31;
            int row = m0 + r;
            if (row < M)
                *(float4*)&outp[(size_t)row * 128 + cq * 4] = *(float4*)&stage[r * ST_STRIDE + cq * 4];
        }
    }
}

// ---------------- fused edge scatter: 2 edges per warp, vec4 atomics ----------------
__global__ void edge_fused_kernel(const int* __restrict__ src,
                                  const int* __restrict__ dst,
                                  const int* __restrict__ lab,
                                  const float* __restrict__ blab_in,
                                  const float* __restrict__ blab_out,
                                  int E, int N) {
    int gw = (int)((blockIdx.x * (unsigned)blockDim.x + threadIdx.x) >> 5);
    int lane = threadIdx.x & 31;
    int e0 = gw * 2;
    if (e0 >= E) return;
    int e1 = e0 + 1;
    bool do1 = (e1 < E);
    if (!do1) e1 = e0;

    int s0 = min(max(src[e0], 0), N - 1), d0 = min(max(dst[e0], 0), N - 1);
    int l0 = min(max(lab[e0], 0), NLAB - 1);
    int s1 = min(max(src[e1], 0), N - 1), d1 = min(max(dst[e1], 0), N - 1);
    int l1 = min(max(lab[e1], 0), NLAB - 1);

    float gi0 = sigmoidf_(g_gate[0][s0] + g_c[0][l0]);
    float go0 = sigmoidf_(g_gate[1][d0] + g_c[1][l0]);
    float gi1 = sigmoidf_(g_gate[0][s1] + g_c[0][l1]);
    float go1 = sigmoidf_(g_gate[1][d1] + g_c[1][l1]);

    float4 mi0 = ((const float4*)g_hin)[(size_t)s0 * 32 + lane];
    float4 mo0 = ((const float4*)g_hout)[(size_t)d0 * 32 + lane];
    float4 mi1 = ((const float4*)g_hin)[(size_t)s1 * 32 + lane];
    float4 mo1 = ((const float4*)g_hout)[(size_t)d1 * 32 + lane];

    float4 bi0 = ((const float4*)blab_in)[l0 * 32 + lane];
    float4 bo0 = ((const float4*)blab_out)[l0 * 32 + lane];
    float4 bi1 = ((const float4*)blab_in)[l1 * 32 + lane];
    float4 bo1 = ((const float4*)blab_out)[l1 * 32 + lane];

    float4 vi0 = make_float4(gi0 * (mi0.x + bi0.x), gi0 * (mi0.y + bi0.y),
                             gi0 * (mi0.z + bi0.z), gi0 * (mi0.w + bi0.w));
    float4 vo0 = make_float4(go0 * (mo0.x + bo0.x), go0 * (mo0.y + bo0.y),
                             go0 * (mo0.z + bo0.z), go0 * (mo0.w + bo0.w));
    atomicAdd(((float4*)g_acc) + (size_t)d0 * 32 + lane, vi0);
    atomicAdd(((float4*)g_acc) + (size_t)s0 * 32 + lane, vo0);

    if (do1) {
        float4 vi1 = make_float4(gi1 * (mi1.x + bi1.x), gi1 * (mi1.y + bi1.y),
                                 gi1 * (mi1.z + bi1.z), gi1 * (mi1.w + bi1.w));
        float4 vo1 = make_float4(go1 * (mo1.x + bo1.x), go1 * (mo1.y + bo1.y),
                                 go1 * (mo1.z + bo1.z), go1 * (mo1.w + bo1.w));
        atomicAdd(((float4*)g_acc) + (size_t)d1 * 32 + lane, vi1);
        atomicAdd(((float4*)g_acc) + (size_t)s1 * 32 + lane, vo1);
    }
}

// ---------------- final relu: g_acc -> d_out ----------------
__global__ void relu_kernel(float* __restrict__ out, int n4) {
    int i = blockIdx.x * blockDim.x + threadIdx.x;
    if (i < n4) {
        float4 v = ((const float4*)g_acc)[i];
        v.x = fmaxf(v.x, 0.f); v.y = fmaxf(v.y, 0.f);
        v.z = fmaxf(v.z, 0.f); v.w = fmaxf(v.w, 0.f);
        ((float4*)out)[i] = v;
    }
}

// ---------------- launch ----------------
extern "C" void kernel_launch(void* const* d_in, const int* in_sizes, int n_in,
                              void* d_out, int out_size) {
    const float* x        = (const float*)d_in[0];
    const int* ei         = (const int*)d_in[1];   // [2, E] int32
    const int* lab        = (const int*)d_in[2];   // [E] int32
    const float* W_loop   = (const float*)d_in[3];
    const float* b_loop   = (const float*)d_in[4];
    const float* Wg_loop  = (const float*)d_in[5];
    const float* bg_loop  = (const float*)d_in[6];
    const float* W_in     = (const float*)d_in[7];
    const float* blab_in  = (const float*)d_in[8];
    const float* Wg_in    = (const float*)d_in[9];
    const float* bg_in    = (const float*)d_in[10];
    const float* W_out    = (const float*)d_in[11];
    const float* blab_out = (const float*)d_in[12];
    const float* Wg_out   = (const float*)d_in[13];
    const float* bg_out   = (const float*)d_in[14];

    int N = in_sizes[0] / DIMS;
    int E = in_sizes[2];

    prep_w2_kernel<<<dim3(DIMS, 2), DIMS>>>(W_in, W_out);
    prep_c_kernel<<<1, 32>>>(Wg_in, blab_in, bg_in, Wg_out, blab_out, bg_out);
    prep_wt_kernel<<<3, 256>>>(W_loop);

    cudaFuncSetAttribute(gemm_mma_kernel, cudaFuncAttributeMaxDynamicSharedMemorySize,
                         GEMM_SMEM);
    gemm_mma_kernel<<<(N + 127) / 128, GTHREADS, GEMM_SMEM>>>(
        x, b_loop, Wg_loop, bg_loop, Wg_in, Wg_out, N);

    int warps = (E + 1) / 2;
    int eblocks = (warps + 7) / 8;
    edge_fused_kernel<<<eblocks, 256>>>(ei, ei + E, lab, blab_in, blab_out, E, N);

    int n4 = N * DIMS / 4;
    relu_kernel<<<(n4 + 255) / 256, 256>>>((float*)d_out, n4);
}

// round 14
// speedup vs baseline: 1.2770x; 1.0208x over previous
#include <cuda_runtime.h>
#include <cstdint>

#define DIMS 128
#define NLAB 5
#define MAXN 50000
#define GTHREADS 512

// ---------------- device scratch ----------------
__device__ float g_W2[2][DIMS * DIMS];        // W_in@W_in, W_out@W_out (fp32)
__device__ float g_Wt[3][DIMS * 144];         // prepacked tf32 B^T images (quad layout)
__device__ float g_c[2][NLAB];                // per-label gate constants
__device__ float g_gate[2][MAXN];             // per-node h.Wg scalars
__device__ float g_hin[MAXN * DIMS];          // x @ (W_in @ W_in)
__device__ float g_hout[MAXN * DIMS];         // x @ (W_out @ W_out)
__device__ float g_acc[MAXN * DIMS];          // accumulator (xl + scatter sums)

__device__ __forceinline__ float sigmoidf_(float x) {
    return 1.0f / (1.0f + __expf(-x));
}

__device__ __forceinline__ float tf32r(float x) {
    uint32_t u;
    asm("cvt.rna.tf32.f32 %0, %1;" : "=r"(u) : "f"(x));
    return __uint_as_float(u);
}

__device__ __forceinline__ void mma_tf32(float* c, uint32_t a0, uint32_t a1,
                                         uint32_t a2, uint32_t a3,
                                         uint32_t b0, uint32_t b1) {
    asm volatile(
        "mma.sync.aligned.m16n8k8.row.col.f32.tf32.tf32.f32 "
        "{%0,%1,%2,%3}, {%4,%5,%6,%7}, {%8,%9}, {%0,%1,%2,%3};"
        : "+f"(c[0]), "+f"(c[1]), "+f"(c[2]), "+f"(c[3])
        : "r"(a0), "r"(a1), "r"(a2), "r"(a3), "r"(b0), "r"(b1));
}

// ---------------- prep: W2 = W @ W ----------------
__global__ void prep_w2_kernel(const float* __restrict__ Win,
                               const float* __restrict__ Wout) {
    __shared__ float wrow[DIMS];
    const float* W = (blockIdx.y == 0) ? Win : Wout;
    int r = blockIdx.x, c = threadIdx.x;
    wrow[c] = W[r * DIMS + c];
    __syncthreads();
    float s = 0.0f;
#pragma unroll 8
    for (int k = 0; k < DIMS; k++) s += wrow[k] * W[k * DIMS + c];
    g_W2[blockIdx.y][r * DIMS + c] = s;
}

// ---------------- prep: gate constants ----------------
__global__ void prep_c_kernel(const float* __restrict__ Wg_in,
                              const float* __restrict__ blab_in,
                              const float* __restrict__ bg_in,
                              const float* __restrict__ Wg_out,
                              const float* __restrict__ blab_out,
                              const float* __restrict__ bg_out) {
    int t = threadIdx.x;
    if (t >= 2 * NLAB) return;
    int w = t / NLAB, l = t % NLAB;
    const float* Wg = w ? Wg_out : Wg_in;
    const float* bl = w ? blab_out : blab_in;
    const float* bg = w ? bg_out : bg_in;
    float s = bg[l];
    for (int d = 0; d < DIMS; d++) s += bl[l * DIMS + d] * Wg[d];
    g_c[w][l] = s;
}

// ---------------- prep: quad-layout tf32 W images ----------------
// B^T row n, k: ks=k>>3, kk=k&7, ks2=ks>>1, par=ks&1, frag=kk>>2, t4k=kk&3
// pos = ks2*16 + t4k*4 + par*2 + frag  ->  one float4 per (ks2,t4) covers both k-steps
__global__ void prep_wt_kernel(const float* __restrict__ Wloop) {
    int w = blockIdx.x;
    const float* W = (w == 0) ? Wloop : g_W2[w - 1];
    for (int idx = threadIdx.x; idx < DIMS * DIMS; idx += blockDim.x) {
        int k = idx >> 7, n = idx & 127;
        float v = W[idx];                 // W[k*128 + n], coalesced
        int ks = k >> 3, kk = k & 7;
        int pos = (ks >> 1) * 16 + (kk & 3) * 4 + (ks & 1) * 2 + (kk >> 2);
        g_Wt[w][n * 144 + pos] = tf32r(v);
    }
}

// ---------------- mma.sync tf32 GEMM: 512 thr, A-frags in regs, B LDS.128 ----------------
#define AS_STRIDE 132
#define WH_STRIDE 144
#define SMEM_AS 0
#define SMEM_WH (128 * AS_STRIDE)
#define ST_STRIDE 132
#define GEMM_SMEM ((128 * AS_STRIDE + 128 * WH_STRIDE) * 4)

__global__ __launch_bounds__(GTHREADS) void gemm_mma_kernel(const float* __restrict__ x,
                                                            const float* __restrict__ b_loop,
                                                            const float* __restrict__ Wg_loop,
                                                            const float* __restrict__ bg_loop,
                                                            const float* __restrict__ Wg_in,
                                                            const float* __restrict__ Wg_out,
                                                            int M) {
    extern __shared__ float smem[];
    float* As = smem + SMEM_AS;
    float* Wh = smem + SMEM_WH;     // reused as store-staging buffer
    __shared__ float sg[DIMS * 2];  // per-row gate-dot partials [row][col-half]

    int tid = threadIdx.x;
    int wid = tid >> 5, lane = tid & 31;
    int g = lane >> 2, t4 = lane & 3;
    int rg = wid & 7;               // row group (16 rows each)
    int ch = wid >> 3;              // column half (64 cols each)
    int m0 = blockIdx.x * 128;
    int m0w = rg * 16;

    // ---- load x tile, tf32-round once ----
    const float4* x4 = (const float4*)x;
#pragma unroll
    for (int i = 0; i < 8; i++) {
        int fidx = tid + i * GTHREADS;
        int r = fidx >> 5, kq = fidx & 31;
        float4 v = make_float4(0.f, 0.f, 0.f, 0.f);
        if (m0 + r < M) v = x4[(size_t)(m0 + r) * 32 + kq];
        v.x = tf32r(v.x); v.y = tf32r(v.y); v.z = tf32r(v.z); v.w = tf32r(v.w);
        *(float4*)&As[r * AS_STRIDE + kq * 4] = v;
    }
    __syncthreads();

    // ---- hoist all A fragments into registers (shared across the 3 weights) ----
    int rloc0 = m0w + g, rloc1 = rloc0 + 8;
    const float* pa0 = As + rloc0 * AS_STRIDE;
    const float* pa1 = As + rloc1 * AS_STRIDE;
    uint32_t af[16][4];
#pragma unroll
    for (int ks = 0; ks < 16; ks++) {
        int k0 = ks * 8;
        af[ks][0] = __float_as_uint(pa0[k0 + t4]);
        af[ks][1] = __float_as_uint(pa1[k0 + t4]);
        af[ks][2] = __float_as_uint(pa0[k0 + t4 + 4]);
        af[ks][3] = __float_as_uint(pa1[k0 + t4 + 4]);
    }

    for (int w = 0; w < 3; w++) {
        // ---- copy prepacked W image into smem ----
        __syncthreads();
        {
            const float4* srcp = (const float4*)g_Wt[w];
            float4* dstp = (float4*)Wh;
#pragma unroll
            for (int i = 0; i < 9; i++) {
                int fi = tid + i * GTHREADS;
                if (fi < 128 * WH_STRIDE / 4) dstp[fi] = srcp[fi];
            }
        }
        __syncthreads();

        // ---- mainloop: warp tile 16 rows x 64 cols, B via LDS.128 ----
        float acc[8][4];
#pragma unroll
        for (int j = 0; j < 8; j++)
#pragma unroll
            for (int q = 0; q < 4; q++) acc[j][q] = 0.0f;

#pragma unroll
        for (int ks2 = 0; ks2 < 8; ks2++) {
            int ke = ks2 * 2, ko = ke + 1;
#pragma unroll
            for (int j = 0; j < 8; j++) {
                int n = (ch * 8 + j) * 8 + g;
                float4 bq = *(const float4*)&Wh[n * WH_STRIDE + ks2 * 16 + t4 * 4];
                mma_tf32(acc[j], af[ke][0], af[ke][1], af[ke][2], af[ke][3],
                         __float_as_uint(bq.x), __float_as_uint(bq.y));
                mma_tf32(acc[j], af[ko][0], af[ko][1], af[ko][2], af[ko][3],
                         __float_as_uint(bq.z), __float_as_uint(bq.w));
            }
        }

        // ---- per-row gate dot partials over this warp's 64 cols ----
        float p0 = 0.f, p1 = 0.f;
        if (w == 0) {
#pragma unroll
            for (int j = 0; j < 8; j++) {
                int c0 = ch * 64 + j * 8 + t4 * 2;
                float2 bl2 = *(const float2*)&b_loop[c0];
                float2 wg2 = *(const float2*)&Wg_loop[c0];
                acc[j][0] += bl2.x; acc[j][1] += bl2.y;
                acc[j][2] += bl2.x; acc[j][3] += bl2.y;
                p0 += acc[j][0] * wg2.x + acc[j][1] * wg2.y;
                p1 += acc[j][2] * wg2.x + acc[j][3] * wg2.y;
            }
        } else {
            const float* Wg = (w == 2) ? Wg_out : Wg_in;
#pragma unroll
            for (int j = 0; j < 8; j++) {
                int c0 = ch * 64 + j * 8 + t4 * 2;
                float2 wg2 = *(const float2*)&Wg[c0];
                p0 += acc[j][0] * wg2.x + acc[j][1] * wg2.y;
                p1 += acc[j][2] * wg2.x + acc[j][3] * wg2.y;
            }
        }
        p0 += __shfl_xor_sync(0xffffffffu, p0, 1);
        p0 += __shfl_xor_sync(0xffffffffu, p0, 2);
        p1 += __shfl_xor_sync(0xffffffffu, p1, 1);
        p1 += __shfl_xor_sync(0xffffffffu, p1, 2);
        if (t4 == 0) {
            sg[rloc0 * 2 + ch] = p0;
            sg[rloc1 * 2 + ch] = p1;
        }
        __syncthreads();   // sg visible; all Wh reads complete

        if (w == 0) {
            float bgv = __ldg(&bg_loop[0]);
            float g0 = sigmoidf_(sg[rloc0 * 2] + sg[rloc0 * 2 + 1] + bgv);
            float g1 = sigmoidf_(sg[rloc1 * 2] + sg[rloc1 * 2 + 1] + bgv);
#pragma unroll
            for (int j = 0; j < 8; j++) {
                acc[j][0] *= g0; acc[j][1] *= g0;
                acc[j][2] *= g1; acc[j][3] *= g1;
            }
        } else {
            int dir = w - 1;
            if (tid < DIMS) {
                int row = m0 + tid;
                if (row < M) g_gate[dir][row] = sg[tid * 2] + sg[tid * 2 + 1];
            }
        }

        // ---- stage into smem (Wh reused), then coalesced float4 stores ----
        float* stage = Wh;
#pragma unroll
        for (int j = 0; j < 8; j++) {
            int c0 = ch * 64 + j * 8 + t4 * 2;
            *(float2*)&stage[rloc0 * ST_STRIDE + c0] = make_float2(acc[j][0], acc[j][1]);
            *(float2*)&stage[rloc1 * ST_STRIDE + c0] = make_float2(acc[j][2], acc[j][3]);
        }
        __syncthreads();

        float* outp = (w == 0) ? g_acc : ((w == 1) ? g_hin : g_hout);
#pragma unroll
        for (int i = 0; i < 8; i++) {
            int fidx = tid + i * GTHREADS;
            int r = fidx >> 5, cq = fidx & 31;
            int row = m0 + r;
            if (row < M)
                *(float4*)&outp[(size_t)row * 128 + cq * 4] = *(float4*)&stage[r * ST_STRIDE + cq * 4];
        }
    }
}

// ---------------- fused edge scatter: 2 edges per warp, vec4 atomics ----------------
__global__ void edge_fused_kernel(const int* __restrict__ src,
                                  const int* __restrict__ dst,
                                  const int* __restrict__ lab,
                                  const float* __restrict__ blab_in,
                                  const float* __restrict__ blab_out,
                                  int E, int N) {
    int gw = (int)((blockIdx.x * (unsigned)blockDim.x + threadIdx.x) >> 5);
    int lane = threadIdx.x & 31;
    int e0 = gw * 2;
    if (e0 >= E) return;
    int e1 = e0 + 1;
    bool do1 = (e1 < E);
    if (!do1) e1 = e0;

    int s0 = min(max(src[e0], 0), N - 1), d0 = min(max(dst[e0], 0), N - 1);
    int l0 = min(max(lab[e0], 0), NLAB - 1);
    int s1 = min(max(src[e1], 0), N - 1), d1 = min(max(dst[e1], 0), N - 1);
    int l1 = min(max(lab[e1], 0), NLAB - 1);

    float gi0 = sigmoidf_(g_gate[0][s0] + g_c[0][l0]);
    float go0 = sigmoidf_(g_gate[1][d0] + g_c[1][l0]);
    float gi1 = sigmoidf_(g_gate[0][s1] + g_c[0][l1]);
    float go1 = sigmoidf_(g_gate[1][d1] + g_c[1][l1]);

    float4 mi0 = ((const float4*)g_hin)[(size_t)s0 * 32 + lane];
    float4 mo0 = ((const float4*)g_hout)[(size_t)d0 * 32 + lane];
    float4 mi1 = ((const float4*)g_hin)[(size_t)s1 * 32 + lane];
    float4 mo1 = ((const float4*)g_hout)[(size_t)d1 * 32 + lane];

    float4 bi0 = ((const float4*)blab_in)[l0 * 32 + lane];
    float4 bo0 = ((const float4*)blab_out)[l0 * 32 + lane];
    float4 bi1 = ((const float4*)blab_in)[l1 * 32 + lane];
    float4 bo1 = ((const float4*)blab_out)[l1 * 32 + lane];

    float4 vi0 = make_float4(gi0 * (mi0.x + bi0.x), gi0 * (mi0.y + bi0.y),
                             gi0 * (mi0.z + bi0.z), gi0 * (mi0.w + bi0.w));
    float4 vo0 = make_float4(go0 * (mo0.x + bo0.x), go0 * (mo0.y + bo0.y),
                             go0 * (mo0.z + bo0.z), go0 * (mo0.w + bo0.w));
    atomicAdd(((float4*)g_acc) + (size_t)d0 * 32 + lane, vi0);
    atomicAdd(((float4*)g_acc) + (size_t)s0 * 32 + lane, vo0);

    if (do1) {
        float4 vi1 = make_float4(gi1 * (mi1.x + bi1.x), gi1 * (mi1.y + bi1.y),
                                 gi1 * (mi1.z + bi1.z), gi1 * (mi1.w + bi1.w));
        float4 vo1 = make_float4(go1 * (mo1.x + bo1.x), go1 * (mo1.y + bo1.y),
                                 go1 * (mo1.z + bo1.z), go1 * (mo1.w + bo1.w));
        atomicAdd(((float4*)g_acc) + (size_t)d1 * 32 + lane, vi1);
        atomicAdd(((float4*)g_acc) + (size_t)s1 * 32 + lane, vo1);
    }
}

// ---------------- final relu: g_acc -> d_out ----------------
__global__ void relu_kernel(float* __restrict__ out, int n4) {
    int i = blockIdx.x * blockDim.x + threadIdx.x;
    if (i < n4) {
        float4 v = ((const float4*)g_acc)[i];
        v.x = fmaxf(v.x, 0.f); v.y = fmaxf(v.y, 0.f);
        v.z = fmaxf(v.z, 0.f); v.w = fmaxf(v.w, 0.f);
        ((float4*)out)[i] = v;
    }
}

// ---------------- launch ----------------
extern "C" void kernel_launch(void* const* d_in, const int* in_sizes, int n_in,
                              void* d_out, int out_size) {
    const float* x        = (const float*)d_in[0];
    const int* ei         = (const int*)d_in[1];   // [2, E] int32
    const int* lab        = (const int*)d_in[2];   // [E] int32
    const float* W_loop   = (const float*)d_in[3];
    const float* b_loop   = (const float*)d_in[4];
    const float* Wg_loop  = (const float*)d_in[5];
    const float* bg_loop  = (const float*)d_in[6];
    const float* W_in     = (const float*)d_in[7];
    const float* blab_in  = (const float*)d_in[8];
    const float* Wg_in    = (const float*)d_in[9];
    const float* bg_in    = (const float*)d_in[10];
    const float* W_out    = (const float*)d_in[11];
    const float* blab_out = (const float*)d_in[12];
    const float* Wg_out   = (const float*)d_in[13];
    const float* bg_out   = (const float*)d_in[14];

    int N = in_sizes[0] / DIMS;
    int E = in_sizes[2];

    prep_w2_kernel<<<dim3(DIMS, 2), DIMS>>>(W_in, W_out);
    prep_c_kernel<<<1, 32>>>(Wg_in, blab_in, bg_in, Wg_out, blab_out, bg_out);
    prep_wt_kernel<<<3, 256>>>(W_loop);

    cudaFuncSetAttribute(gemm_mma_kernel, cudaFuncAttributeMaxDynamicSharedMemorySize,
                         GEMM_SMEM);
    gemm_mma_kernel<<<(N + 127) / 128, GTHREADS, GEMM_SMEM>>>(
        x, b_loop, Wg_loop, bg_loop, Wg_in, Wg_out, N);

    int warps = (E + 1) / 2;
    int eblocks = (warps + 7) / 8;
    edge_fused_kernel<<<eblocks, 256>>>(ei, ei + E, lab, blab_in, blab_out, E, N);

    int n4 = N * DIMS / 4;
    relu_kernel<<<(n4 + 255) / 256, 256>>>((float*)d_out, n4);
}